// round 12
// baseline (speedup 1.0000x reference)
#include <cuda_runtime.h>
#include <cstdint>
#include <cstddef>

// out[b] = weight[b] + top1000_scatter_mask(|difference[b]|), B=64, N=1M/batch.
// R12: fused kernel, cheap publication. R11's regression was 256x per-block
// gpu-scope __threadfence (CCTL.IVALL + MEMBAR each). Now: one release-scoped
// ticket atomic per block (thread 0, after __syncthreads); the selection block
// does a single acq_rel fence before consuming.

namespace {

constexpr int B      = 64;
constexpr int NPB    = 1 << 20;
constexpr int TOPN   = 1000;
constexpr unsigned CUT = 0x404CCCCDu; // float bits of 3.2f (rank-1000 ~3.29 sigma)
constexpr int BPB    = 1024;          // blocks per batch
constexpr int DCAP   = 16384;         // dense candidate capacity (mean ~1374)
constexpr int NBIN   = 4096;          // fine bins: (key - CUT) >> 12, clamped
constexpr int BCAP   = 1024;          // boundary list capacity (reuses s_key/s_idx)

__device__ unsigned g_dkey[B][DCAP];
__device__ unsigned g_didx[B][DCAP];
__device__ unsigned g_dcnt[B * 32];   // 128B-padded; reset by selection block
__device__ unsigned g_done[B * 32];   // completion tickets; reset by selection block
__device__ unsigned g_hist[B][NBIN];  // built by all blocks; zeroed by selection block

__device__ __forceinline__ unsigned keybin(unsigned key) {
    unsigned d = key - CUT;           // key >= CUT on candidate path
    unsigned bi = d >> 12;
    return bi < (unsigned)NBIN ? bi : (unsigned)(NBIN - 1);
}

// Ticket with release semantics: orders this thread's prior global stores
// (and, via the preceding __syncthreads, the whole block's) before the add.
__device__ __forceinline__ unsigned ticket_release(unsigned* p) {
    unsigned old;
    asm volatile("atom.release.gpu.add.u32 %0, [%1], 1;"
                 : "=r"(old) : "l"(p) : "memory");
    return old;
}

__global__ void __launch_bounds__(256, 8)
k_fused(const float4* __restrict__ diff, const float4* __restrict__ w,
        float4* __restrict__ out, const int* __restrict__ ep) {
    __shared__ unsigned s_key[1024];
    __shared__ unsigned s_idx[1024];
    __shared__ unsigned s_hist[NBIN];          // selection-phase only
    __shared__ unsigned s_wsum[8], s_wsuf[8];
    __shared__ unsigned s_n, s_base, s_rank;
    __shared__ unsigned s_p0, s_rem, s_m, s_bn;
    __shared__ unsigned s_prefix, s_rem2, s_tcnt;

    unsigned tid = threadIdx.x;
    if (tid == 0) s_n = 0u;
    __syncthreads();

    // ---------------- Streaming phase (every block) ----------------
    unsigned b    = blockIdx.x & 63u;          // interleaved batch mapping
    unsigned bblk = blockIdx.x >> 6;
    unsigned t    = (b << 18) + bblk * 256u + tid;
    float4 d = __ldcs(&diff[t]);
    __stcs(&out[t], __ldcs(&w[t]));

    unsigned e0 = (bblk * 256u + tid) << 2;

    unsigned keys[4] = {__float_as_uint(d.x) & 0x7FFFFFFFu,
                        __float_as_uint(d.y) & 0x7FFFFFFFu,
                        __float_as_uint(d.z) & 0x7FFFFFFFu,
                        __float_as_uint(d.w) & 0x7FFFFFFFu};
#pragma unroll
    for (int j = 0; j < 4; ++j) {
        if (keys[j] >= CUT) {                  // ~0.137% of elements
            unsigned p = atomicAdd(&s_n, 1u);
            s_key[p] = keys[j];
            s_idx[p] = e0 + j;
        }
    }
    __syncthreads();

    unsigned n = s_n;
    if (n) {
        if (tid == 0)
            s_base = atomicAdd(&g_dcnt[b * 32], n);
        __syncthreads();
        unsigned base = s_base;
        for (unsigned i = tid; i < n; i += 256u) {
            unsigned k = s_key[i];
            unsigned slot = base + i;
            if (slot < (unsigned)DCAP) {
                g_dkey[b][slot] = k;
                g_didx[b][slot] = s_idx[i];
            }
            atomicAdd(&g_hist[b][keybin(k)], 1u);   // ~1.4/block, spread: hidden
        }
    }
    __syncthreads();

    // ---------------- Completion ticket (cheap release) ----------------
    if (tid == 0) s_rank = ticket_release(&g_done[b * 32]);
    __syncthreads();
    if (s_rank != (unsigned)(BPB - 1)) return;

    // ============ Selection (last block of batch b only) ============
    asm volatile("fence.acq_rel.gpu;" ::: "memory");   // acquire others' writes

    float* outf = (float*)out;                 // scalar view for scatter
    const float* diffs = (const float*)diff;
    unsigned lane = tid & 31u, wrp = tid >> 5;
    int epoch = ep[0];
    bool hot = (epoch > 1000) && (epoch < 18000) && (epoch % 200 == 0);

    unsigned raw = g_dcnt[b * 32];
    bool fast = (raw >= (unsigned)TOPN) && (raw <= (unsigned)DCAP);
    size_t gbase = (size_t)b * (size_t)NPB;
    unsigned dom = fast ? raw : (unsigned)NPB;

    bool done_sel = !hot;

    if (hot && fast) {
        // ---- Load histogram to smem (L2-warm), compute chunk sums ----
        unsigned P = 0;
#pragma unroll
        for (int q = 0; q < 4; ++q) {
            uint4 v = ((const uint4*)&g_hist[b][0])[tid * 4u + q];
            ((uint4*)s_hist)[tid * 4u + q] = v;
            P += v.x + v.y + v.z + v.w;
        }
        if (tid == 0) s_bn = 0u;

        // ---- 2-level inclusive suffix scan (256 chunks of 16 bins) ----
        unsigned s = P;
#pragma unroll
        for (unsigned off = 1; off < 32; off <<= 1) {
            unsigned v = __shfl_down_sync(0xFFFFFFFFu, s, off);
            if (lane + off < 32u) s += v;
        }
        if (lane == 0) s_wsum[wrp] = s;
        __syncthreads();
        if (tid == 0) {
            unsigned acc = 0;
            for (int wi = 7; wi >= 0; --wi) { s_wsuf[wi] = acc; acc += s_wsum[wi]; }
        }
        __syncthreads();
        unsigned above = (s + s_wsuf[wrp]) - P;   // keys strictly above my chunk
        unsigned acc = above;
#pragma unroll
        for (int q = 15; q >= 0; --q) {
            unsigned bin = tid * 16u + (unsigned)q;
            unsigned hq  = s_hist[bin];
            if (acc < (unsigned)TOPN && acc + hq >= (unsigned)TOPN) {
                s_p0 = bin; s_rem = (unsigned)TOPN - acc; s_m = hq;
            }
            acc += hq;
        }
        __syncthreads();

        unsigned p0 = s_p0, rem = s_rem, m = s_m;

        if (m <= (unsigned)BCAP) {
            // ---- Single pass: scatter winners, collect boundary bin ----
            for (unsigned i = tid; i < dom; i += 256u) {
                unsigned k  = g_dkey[b][i];
                unsigned bi = keybin(k);
                if (bi > p0) {
                    outf[gbase + g_didx[b][i]] += 1.0f;
                } else if (bi == p0) {
                    unsigned p = atomicAdd(&s_bn, 1u);
                    s_key[p] = k;                    // p < m <= BCAP
                    s_idx[p] = g_didx[b][i];
                }
            }
            __syncthreads();
            // ---- Exact boundary ranking (key desc, idx asc) ----
            for (unsigned u = tid; u < m; u += 256u) {
                unsigned mk = s_key[u], mi = s_idx[u];
                unsigned rank = 0u;
                for (unsigned j = 0; j < m; ++j) {
                    unsigned kj = s_key[j];
                    rank += (kj > mk || (kj == mk && s_idx[j] < mi)) ? 1u : 0u;
                }
                if (rank < rem) outf[gbase + mi] += 1.0f;
            }
            done_sel = true;
        }
        __syncthreads();
    }

    if (!done_sel) {
        // ==== Fallback: exact 4-round radix select (unreachable on bench) ====
        if (tid == 0) { s_prefix = 0u; s_rem2 = (unsigned)TOPN; s_tcnt = 0u; }
        __syncthreads();

        auto getkey = [&](unsigned i) -> unsigned {
            if (fast) return g_dkey[b][i];
            return __float_as_uint(diffs[gbase + i]) & 0x7FFFFFFFu;
        };
        auto getidx = [&](unsigned i) -> unsigned {
            if (fast) return g_didx[b][i];
            return i;
        };

        const int      SH[4] = {23, 15, 7, 0};
        const unsigned BM[4] = {255u, 255u, 255u, 127u};
#pragma unroll 1
        for (int r = 0; r < 4; ++r) {
            if (tid < 256u) s_hist[tid] = 0u;
            __syncthreads();
            int      sh     = SH[r];
            int      hish   = sh + (r == 3 ? 7 : 8);
            unsigned prefix = s_prefix;
            for (unsigned i = tid; i < dom; i += 256u) {
                unsigned key = getkey(i);
                if (((key ^ prefix) >> hish) == 0u)
                    atomicAdd(&s_hist[(key >> sh) & BM[r]], 1u);
            }
            __syncthreads();
            if (tid == 0) {
                unsigned need = s_rem2, a2 = 0u;
                int bin = (int)BM[r];
                for (; bin > 0; --bin) {
                    unsigned c = s_hist[bin];
                    if (a2 + c >= need) break;
                    a2 += c;
                }
                s_rem2   = need - a2;
                s_prefix = prefix | ((unsigned)bin << sh);
            }
            __syncthreads();
        }

        unsigned thr = s_prefix, req = s_rem2;

        for (unsigned i = tid; i < dom; i += 256u) {
            unsigned key = getkey(i);
            if (key > thr) {
                outf[gbase + getidx(i)] += 1.0f;
            } else if (key == thr) {
                unsigned p = atomicAdd(&s_tcnt, 1u);
                if (p < (unsigned)BCAP) s_key[p] = getidx(i);
            }
        }
        __syncthreads();

        unsigned tc = s_tcnt;
        if (tc <= (unsigned)BCAP) {
            for (unsigned u = tid; u < tc; u += 256u) {
                unsigned my = s_key[u], rank = 0u;
                for (unsigned j = 0; j < tc; ++j) rank += (s_key[j] < my) ? 1u : 0u;
                if (rank < req) outf[gbase + my] += 1.0f;
            }
        } else {
            for (unsigned i = tid; i < dom; i += 256u) {
                unsigned key = getkey(i);
                if (key != thr) continue;
                unsigned idx = getidx(i), rank = 0u;
                for (unsigned j = 0; j < dom; ++j) {
                    if (getkey(j) == thr && getidx(j) < idx) ++rank;
                }
                if (rank < req) outf[gbase + idx] += 1.0f;
            }
        }
        __syncthreads();
    }

    // ---- Epilogue: reset per-batch state for the next graph replay ----
    for (unsigned i = tid; i < (unsigned)NBIN; i += 256u) g_hist[b][i] = 0u;
    if (tid == 0) { g_dcnt[b * 32] = 0u; g_done[b * 32] = 0u; }
}

} // namespace

extern "C" void kernel_launch(void* const* d_in, const int* in_sizes, int n_in,
                              void* d_out, int out_size) {
    const float* diff = (const float*)d_in[0];
    const float* w    = (const float*)d_in[1];
    const int*   ep   = (const int*)d_in[2];
    float*       out  = (float*)d_out;

    k_fused<<<B * BPB, 256>>>((const float4*)diff, (const float4*)w,
                              (float4*)out, ep);
}

// round 13
// speedup vs baseline: 1.4547x; 1.4547x over previous
#include <cuda_runtime.h>
#include <cstdint>
#include <cstddef>

// out[b] = weight[b] + top1000_scatter_mask(|difference[b]|), B=64, N=1M/batch.
// R13 = R9 (proven two-kernel, 135.4us) + REDG scatter: out[idx] += 1 becomes
// atomicAdd with discarded result -> RED.E.ADD.F32, removing the DRAM RMW
// round-trip from k_select's critical path. Fusion (R10-R12) abandoned.

namespace {

constexpr int B      = 64;
constexpr int NPB    = 1 << 20;
constexpr int TOPN   = 1000;
constexpr unsigned CUT = 0x404CCCCDu; // float bits of 3.2f (rank-1000 ~3.29 sigma)
constexpr int BPB    = 1024;
constexpr int DCAP   = 16384;         // dense candidate capacity (mean ~1374)
constexpr int NBIN   = 4096;          // fine bins: (key - CUT) >> 12, clamped
constexpr int BCAP   = 1024;          // boundary-bin capacity (mean ~3)
constexpr int MAXTIES = 256;
constexpr int STH    = 1024;

__device__ unsigned g_dkey[B][DCAP];
__device__ unsigned g_didx[B][DCAP];
__device__ unsigned g_dcnt[B * 32];   // 128B-padded; reset by k_select each replay
__device__ unsigned g_hist[B][NBIN];  // built by k_main; zeroed by k_select

__device__ __forceinline__ unsigned keybin(unsigned key) {
    unsigned d = key - CUT;           // key >= CUT on candidate path
    unsigned bi = d >> 12;
    return bi < (unsigned)NBIN ? bi : (unsigned)(NBIN - 1);
}

// Fire-and-forget +1.0 (REDG): no load-modify-store round trip.
__device__ __forceinline__ void scatter1(float* p) {
    atomicAdd(p, 1.0f);               // result unused -> RED.E.ADD.F32
}

// Streaming pass: out = weight; gather |diff| >= 3.2 + per-batch fine histogram.
// (Byte-identical logic to R9's k_main — pinned at the LTS cap, do not touch.)
__global__ void __launch_bounds__(256) k_main(const float4* __restrict__ diff,
                                              const float4* __restrict__ w,
                                              float4* __restrict__ out) {
    __shared__ unsigned s_key[1024];
    __shared__ unsigned s_idx[1024];
    __shared__ unsigned s_n, s_base;
    if (threadIdx.x == 0) s_n = 0u;
    __syncthreads();

    unsigned b    = blockIdx.x & 63u;          // interleaved batch mapping
    unsigned bblk = blockIdx.x >> 6;
    unsigned t    = (b << 18) + bblk * 256u + threadIdx.x;
    float4 d = __ldcs(&diff[t]);
    __stcs(&out[t], __ldcs(&w[t]));

    unsigned e0 = (bblk * 256u + threadIdx.x) << 2;

    unsigned keys[4] = {__float_as_uint(d.x) & 0x7FFFFFFFu,
                        __float_as_uint(d.y) & 0x7FFFFFFFu,
                        __float_as_uint(d.z) & 0x7FFFFFFFu,
                        __float_as_uint(d.w) & 0x7FFFFFFFu};
#pragma unroll
    for (int j = 0; j < 4; ++j) {
        if (keys[j] >= CUT) {                 // ~0.137% of elements
            unsigned p = atomicAdd(&s_n, 1u);
            s_key[p] = keys[j];
            s_idx[p] = e0 + j;
        }
    }
    __syncthreads();

    unsigned n = s_n;
    if (n) {
        if (threadIdx.x == 0)
            s_base = atomicAdd(&g_dcnt[b * 32], n);
        __syncthreads();
        unsigned base = s_base;
        for (unsigned i = threadIdx.x; i < n; i += 256u) {
            unsigned k = s_key[i];
            unsigned slot = base + i;
            if (slot < (unsigned)DCAP) {
                g_dkey[b][slot] = k;
                g_didx[b][slot] = s_idx[i];
            }
            atomicAdd(&g_hist[b][keybin(k)], 1u);  // ~1.4/block, spread: hidden
        }
    }
}

// Per-batch selection: hist scan + one short candidate pass. One block/batch.
__global__ void __launch_bounds__(STH) k_select(const float* __restrict__ diff,
                                                float* __restrict__ out,
                                                const int* __restrict__ ep) {
    __shared__ unsigned hist[NBIN];
    __shared__ unsigned s_wsum[32], s_wsuf[32];
    __shared__ unsigned s_bkey[BCAP];
    __shared__ unsigned s_bidx[BCAP];
    __shared__ unsigned s_bn, s_p0, s_rem;
    __shared__ unsigned s_prefix, s_rem2, s_tcnt;
    __shared__ unsigned s_tidx[MAXTIES];

    int b = blockIdx.x;
    unsigned tid  = threadIdx.x;
    unsigned lane = tid & 31u;
    unsigned wid  = tid >> 5;
    int epoch = ep[0];
    bool hot = (epoch > 1000) && (epoch < 18000) && (epoch % 200 == 0);

    unsigned raw = g_dcnt[b * 32];
    bool fast = (raw >= (unsigned)TOPN) && (raw <= (unsigned)DCAP);
    size_t gbase = (size_t)b * (size_t)NPB;
    unsigned dom = fast ? raw : (unsigned)NPB;

    bool done = !hot;

    if (hot && fast) {
        // ---- Load per-batch histogram (coalesced, 4 per thread) ----
        unsigned h0 = g_hist[b][tid * 4 + 0], h1 = g_hist[b][tid * 4 + 1];
        unsigned h2 = g_hist[b][tid * 4 + 2], h3 = g_hist[b][tid * 4 + 3];
        hist[tid * 4 + 0] = h0; hist[tid * 4 + 1] = h1;
        hist[tid * 4 + 2] = h2; hist[tid * 4 + 3] = h3;
        if (tid == 0) s_bn = 0u;

        // ---- Warp-shuffle inclusive suffix scan over 1024 chunk sums ----
        unsigned P = h0 + h1 + h2 + h3;
        unsigned s = P;
#pragma unroll
        for (unsigned off = 1; off < 32; off <<= 1) {
            unsigned v = __shfl_down_sync(0xFFFFFFFFu, s, off);
            if (lane + off < 32u) s += v;
        }
        if (lane == 0) s_wsum[wid] = s;      // whole-warp sum
        __syncthreads();
        if (wid == 0) {
            unsigned tsum = s_wsum[lane];
            unsigned ss = tsum;
#pragma unroll
            for (unsigned off = 1; off < 32; off <<= 1) {
                unsigned v = __shfl_down_sync(0xFFFFFFFFu, ss, off);
                if (lane + off < 32u) ss += v;
            }
            s_wsuf[lane] = ss - tsum;        // sum of warps strictly after
        }
        __syncthreads();
        unsigned suffix_incl = s + s_wsuf[wid];  // keys in chunks tid..1023
        unsigned above = suffix_incl - P;        // keys strictly above chunk
        unsigned acc = above;
        unsigned hh[4] = {h3, h2, h1, h0};
#pragma unroll
        for (int q = 0; q < 4; ++q) {
            unsigned bin = tid * 4u + (3u - q);
            if (acc < (unsigned)TOPN && acc + hh[q] >= (unsigned)TOPN) {
                s_p0 = bin; s_rem = (unsigned)TOPN - acc;
            }
            acc += hh[q];
        }
        __syncthreads();

        unsigned p0  = s_p0;
        unsigned rem = s_rem;
        unsigned m   = hist[p0];

        if (m <= (unsigned)BCAP) {
            // ---- Single short pass: REDG-scatter winners, collect boundary --
            for (unsigned i = tid; i < dom; i += STH) {
                unsigned k  = g_dkey[b][i];
                unsigned bi = keybin(k);
                if (bi > p0) {
                    scatter1(&out[gbase + g_didx[b][i]]);
                } else if (bi == p0) {
                    unsigned p = atomicAdd(&s_bn, 1u);
                    s_bkey[p] = k;                     // p < m <= BCAP
                    s_bidx[p] = g_didx[b][i];
                }
            }
            __syncthreads();
            // ---- Exact boundary ranking (key desc, idx asc) ----
            for (unsigned u = tid; u < m; u += STH) {
                unsigned mk = s_bkey[u], mi = s_bidx[u];
                unsigned rank = 0u;
                for (unsigned j = 0; j < m; ++j) {
                    unsigned kj = s_bkey[j];
                    rank += (kj > mk || (kj == mk && s_bidx[j] < mi)) ? 1u : 0u;
                }
                if (rank < rem) scatter1(&out[gbase + mi]);
            }
            done = true;
        }
        __syncthreads();
    }

    if (!done) {
        // ==== Fallback: exact 4-round radix select over full batch ====
        if (tid == 0) { s_prefix = 0u; s_rem2 = (unsigned)TOPN; s_tcnt = 0u; }
        __syncthreads();

        auto getkey = [&](unsigned i) -> unsigned {
            if (fast) return g_dkey[b][i];
            return __float_as_uint(diff[gbase + i]) & 0x7FFFFFFFu;
        };
        auto getidx = [&](unsigned i) -> unsigned {
            if (fast) return g_didx[b][i];
            return i;
        };

        const int      SH[4] = {23, 15, 7, 0};
        const unsigned BM[4] = {255u, 255u, 255u, 127u};
#pragma unroll 1
        for (int r = 0; r < 4; ++r) {
            if (tid < 256u) hist[tid] = 0u;
            __syncthreads();
            int      sh     = SH[r];
            int      hish   = sh + (r == 3 ? 7 : 8);
            unsigned prefix = s_prefix;
            for (unsigned i = tid; i < dom; i += STH) {
                unsigned key = getkey(i);
                if (((key ^ prefix) >> hish) == 0u)
                    atomicAdd(&hist[(key >> sh) & BM[r]], 1u);
            }
            __syncthreads();
            if (tid == 0) {
                unsigned need = s_rem2, acc = 0u;
                int bin = (int)BM[r];
                for (; bin > 0; --bin) {
                    unsigned c = hist[bin];
                    if (acc + c >= need) break;
                    acc += c;
                }
                s_rem2   = need - acc;
                s_prefix = prefix | ((unsigned)bin << sh);
            }
            __syncthreads();
        }

        unsigned thr = s_prefix;
        unsigned req = s_rem2;

        for (unsigned i = tid; i < dom; i += STH) {
            unsigned key = getkey(i);
            if (key > thr) {
                scatter1(&out[gbase + getidx(i)]);
            } else if (key == thr) {
                unsigned p = atomicAdd(&s_tcnt, 1u);
                if (p < (unsigned)MAXTIES) s_tidx[p] = getidx(i);
            }
        }
        __syncthreads();

        unsigned tc = s_tcnt;
        if (tc <= (unsigned)MAXTIES) {
            for (unsigned u = tid; u < tc; u += STH) {
                unsigned my = s_tidx[u], rank = 0u;
                for (unsigned j = 0; j < tc; ++j) rank += (s_tidx[j] < my) ? 1u : 0u;
                if (rank < req) scatter1(&out[gbase + my]);
            }
        } else {
            for (unsigned i = tid; i < dom; i += STH) {
                unsigned key = getkey(i);
                if (key != thr) continue;
                unsigned idx = getidx(i), rank = 0u;
                for (unsigned j = 0; j < dom; ++j) {
                    if (getkey(j) == thr && getidx(j) < idx) ++rank;
                }
                if (rank < req) scatter1(&out[gbase + idx]);
            }
        }
        __syncthreads();
    }

    // Epilogue (all paths): zero this batch's histogram + counter for next replay.
#pragma unroll
    for (int q = 0; q < 4; ++q) g_hist[b][tid * 4u + q] = 0u;
    if (tid == 0) g_dcnt[b * 32] = 0u;
}

} // namespace

extern "C" void kernel_launch(void* const* d_in, const int* in_sizes, int n_in,
                              void* d_out, int out_size) {
    const float* diff = (const float*)d_in[0];
    const float* w    = (const float*)d_in[1];
    const int*   ep   = (const int*)d_in[2];
    float*       out  = (float*)d_out;

    k_main<<<B * BPB, 256>>>((const float4*)diff, (const float4*)w, (float4*)out);
    k_select<<<B, STH>>>(diff, out, ep);
}

// round 14
// speedup vs baseline: 1.4760x; 1.0146x over previous
#include <cuda_runtime.h>
#include <cstdint>
#include <cstddef>

// out[b] = weight[b] + top1000_scatter_mask(|difference[b]|), B=64, N=1M/batch.
// R14: g_hist deleted. k_select rebuilds a 1024-bin histogram in SMEM from the
// ~1374 candidates it loads anyway (stashed in smem), then one scatter pass.
// Removes per-batch 16KB hist load + 16KB hist zero + k_main's hist atomics.

namespace {

constexpr int B      = 64;
constexpr int NPB    = 1 << 20;
constexpr int TOPN   = 1000;
constexpr unsigned CUT = 0x404CCCCDu; // float bits of 3.2f (rank-1000 ~3.29 sigma)
constexpr int BPB    = 1024;
constexpr int DCAP   = 16384;         // dense candidate capacity (mean ~1374)
constexpr int CACHE  = 4096;          // smem candidate cache (mean 1374, +70 sigma)
constexpr int NBIN   = 1024;          // smem hist bins: (key - CUT) >> 14, clamped
constexpr int BCAP   = 512;           // boundary-bin capacity (mean ~13)
constexpr int MAXTIES = 256;
constexpr int STH    = 1024;

__device__ unsigned g_dkey[B][DCAP];
__device__ unsigned g_didx[B][DCAP];
__device__ unsigned g_dcnt[B * 32];   // 128B-padded; reset by k_select each replay

__device__ __forceinline__ unsigned keybin(unsigned key) {
    unsigned d = key - CUT;           // key >= CUT on candidate path
    unsigned bi = d >> 14;
    return bi < (unsigned)NBIN ? bi : (unsigned)(NBIN - 1);
}

// Fire-and-forget +1.0 (REDG): no load-modify-store round trip.
__device__ __forceinline__ void scatter1(float* p) {
    atomicAdd(p, 1.0f);               // result unused -> RED.E.ADD.F32
}

// Streaming pass: out = weight; gather |diff| >= 3.2 into dense per-batch arrays.
__global__ void __launch_bounds__(256) k_main(const float4* __restrict__ diff,
                                              const float4* __restrict__ w,
                                              float4* __restrict__ out) {
    __shared__ unsigned s_key[1024];
    __shared__ unsigned s_idx[1024];
    __shared__ unsigned s_n, s_base;
    if (threadIdx.x == 0) s_n = 0u;
    __syncthreads();

    unsigned b    = blockIdx.x & 63u;          // interleaved batch mapping
    unsigned bblk = blockIdx.x >> 6;
    unsigned t    = (b << 18) + bblk * 256u + threadIdx.x;
    float4 d = __ldcs(&diff[t]);
    __stcs(&out[t], __ldcs(&w[t]));

    unsigned e0 = (bblk * 256u + threadIdx.x) << 2;

    unsigned keys[4] = {__float_as_uint(d.x) & 0x7FFFFFFFu,
                        __float_as_uint(d.y) & 0x7FFFFFFFu,
                        __float_as_uint(d.z) & 0x7FFFFFFFu,
                        __float_as_uint(d.w) & 0x7FFFFFFFu};
#pragma unroll
    for (int j = 0; j < 4; ++j) {
        if (keys[j] >= CUT) {                 // ~0.137% of elements
            unsigned p = atomicAdd(&s_n, 1u);
            s_key[p] = keys[j];
            s_idx[p] = e0 + j;
        }
    }
    __syncthreads();

    unsigned n = s_n;
    if (n) {
        if (threadIdx.x == 0)
            s_base = atomicAdd(&g_dcnt[b * 32], n);
        __syncthreads();
        unsigned base = s_base;
        for (unsigned i = threadIdx.x; i < n; i += 256u) {
            unsigned slot = base + i;
            if (slot < (unsigned)DCAP) {
                g_dkey[b][slot] = s_key[i];
                g_didx[b][slot] = s_idx[i];
            }
        }
    }
}

// Per-batch selection, fully self-contained in SMEM. One block per batch.
__global__ void __launch_bounds__(STH) k_select(const float* __restrict__ diff,
                                                float* __restrict__ out,
                                                const int* __restrict__ ep) {
    __shared__ unsigned sk[CACHE];
    __shared__ unsigned si[CACHE];
    __shared__ unsigned hist[NBIN];
    __shared__ unsigned s_wsum[32], s_wsuf[32];
    __shared__ unsigned s_bkey[BCAP];
    __shared__ unsigned s_bidx[BCAP];
    __shared__ unsigned s_bn, s_p0, s_rem;
    __shared__ unsigned s_prefix, s_rem2, s_tcnt;
    __shared__ unsigned s_tidx[MAXTIES];

    int b = blockIdx.x;
    unsigned tid  = threadIdx.x;
    unsigned lane = tid & 31u;
    unsigned wid  = tid >> 5;
    int epoch = ep[0];
    bool hot = (epoch > 1000) && (epoch < 18000) && (epoch % 200 == 0);

    unsigned raw = g_dcnt[b * 32];
    bool fast = (raw >= (unsigned)TOPN) && (raw <= (unsigned)DCAP);
    bool sfit = fast && (raw <= (unsigned)CACHE);
    size_t gbase = (size_t)b * (size_t)NPB;
    unsigned dom = fast ? raw : (unsigned)NPB;

    bool done = !hot;

    if (hot && fast) {
        // ---- Pass A: load candidates once, stash in smem, build smem hist ----
        hist[tid] = 0u;
        if (tid == 0) s_bn = 0u;
        __syncthreads();
        for (unsigned i = tid; i < dom; i += STH) {
            unsigned k  = g_dkey[b][i];
            unsigned id = g_didx[b][i];
            if (sfit) { sk[i] = k; si[i] = id; }
            atomicAdd(&hist[keybin(k)], 1u);      // ~370 live bins: no hot spot
        }
        __syncthreads();

        // ---- Suffix scan over 1024 bins: exactly 1 bin per thread ----
        unsigned P = hist[tid];
        unsigned s = P;
#pragma unroll
        for (unsigned off = 1; off < 32; off <<= 1) {
            unsigned v = __shfl_down_sync(0xFFFFFFFFu, s, off);
            if (lane + off < 32u) s += v;
        }
        if (lane == 0) s_wsum[wid] = s;          // whole-warp sum
        __syncthreads();
        if (wid == 0) {
            unsigned tsum = s_wsum[lane];
            unsigned ss = tsum;
#pragma unroll
            for (unsigned off = 1; off < 32; off <<= 1) {
                unsigned v = __shfl_down_sync(0xFFFFFFFFu, ss, off);
                if (lane + off < 32u) ss += v;
            }
            s_wsuf[lane] = ss - tsum;            // warps strictly after
        }
        __syncthreads();
        unsigned above = (s + s_wsuf[wid]) - P;  // keys in bins strictly above tid
        if (above < (unsigned)TOPN && above + P >= (unsigned)TOPN) {
            s_p0 = tid; s_rem = (unsigned)TOPN - above;
        }
        __syncthreads();

        unsigned p0  = s_p0;
        unsigned rem = s_rem;
        unsigned m   = hist[p0];

        if (m <= (unsigned)BCAP) {
            // ---- Pass B (smem): REDG-scatter winners, collect boundary bin ----
            for (unsigned i = tid; i < dom; i += STH) {
                unsigned k  = sfit ? sk[i] : g_dkey[b][i];
                unsigned bi = keybin(k);
                if (bi > p0) {
                    scatter1(&out[gbase + (sfit ? si[i] : g_didx[b][i])]);
                } else if (bi == p0) {
                    unsigned p = atomicAdd(&s_bn, 1u);
                    s_bkey[p] = k;                       // p < m <= BCAP
                    s_bidx[p] = sfit ? si[i] : g_didx[b][i];
                }
            }
            __syncthreads();
            // ---- Exact boundary ranking (key desc, idx asc) ----
            for (unsigned u = tid; u < m; u += STH) {
                unsigned mk = s_bkey[u], mi = s_bidx[u];
                unsigned rank = 0u;
                for (unsigned j = 0; j < m; ++j) {
                    unsigned kj = s_bkey[j];
                    rank += (kj > mk || (kj == mk && s_bidx[j] < mi)) ? 1u : 0u;
                }
                if (rank < rem) scatter1(&out[gbase + mi]);
            }
            done = true;
        }
        __syncthreads();
    }

    if (!done) {
        // ==== Fallback: exact 4-round radix select over full batch ====
        if (tid == 0) { s_prefix = 0u; s_rem2 = (unsigned)TOPN; s_tcnt = 0u; }
        __syncthreads();

        auto getkey = [&](unsigned i) -> unsigned {
            if (fast) return g_dkey[b][i];
            return __float_as_uint(diff[gbase + i]) & 0x7FFFFFFFu;
        };
        auto getidx = [&](unsigned i) -> unsigned {
            if (fast) return g_didx[b][i];
            return i;
        };

        const int      SH[4] = {23, 15, 7, 0};
        const unsigned BM[4] = {255u, 255u, 255u, 127u};
#pragma unroll 1
        for (int r = 0; r < 4; ++r) {
            if (tid < 256u) hist[tid] = 0u;
            __syncthreads();
            int      sh     = SH[r];
            int      hish   = sh + (r == 3 ? 7 : 8);
            unsigned prefix = s_prefix;
            for (unsigned i = tid; i < dom; i += STH) {
                unsigned key = getkey(i);
                if (((key ^ prefix) >> hish) == 0u)
                    atomicAdd(&hist[(key >> sh) & BM[r]], 1u);
            }
            __syncthreads();
            if (tid == 0) {
                unsigned need = s_rem2, acc = 0u;
                int bin = (int)BM[r];
                for (; bin > 0; --bin) {
                    unsigned c = hist[bin];
                    if (acc + c >= need) break;
                    acc += c;
                }
                s_rem2   = need - acc;
                s_prefix = prefix | ((unsigned)bin << sh);
            }
            __syncthreads();
        }

        unsigned thr = s_prefix;
        unsigned req = s_rem2;

        for (unsigned i = tid; i < dom; i += STH) {
            unsigned key = getkey(i);
            if (key > thr) {
                scatter1(&out[gbase + getidx(i)]);
            } else if (key == thr) {
                unsigned p = atomicAdd(&s_tcnt, 1u);
                if (p < (unsigned)MAXTIES) s_tidx[p] = getidx(i);
            }
        }
        __syncthreads();

        unsigned tc = s_tcnt;
        if (tc <= (unsigned)MAXTIES) {
            for (unsigned u = tid; u < tc; u += STH) {
                unsigned my = s_tidx[u], rank = 0u;
                for (unsigned j = 0; j < tc; ++j) rank += (s_tidx[j] < my) ? 1u : 0u;
                if (rank < req) scatter1(&out[gbase + my]);
            }
        } else {
            for (unsigned i = tid; i < dom; i += STH) {
                unsigned key = getkey(i);
                if (key != thr) continue;
                unsigned idx = getidx(i), rank = 0u;
                for (unsigned j = 0; j < dom; ++j) {
                    if (getkey(j) == thr && getidx(j) < idx) ++rank;
                }
                if (rank < req) scatter1(&out[gbase + idx]);
            }
        }
        __syncthreads();
    }

    if (tid == 0) g_dcnt[b * 32] = 0u;   // reset for next graph replay
}

} // namespace

extern "C" void kernel_launch(void* const* d_in, const int* in_sizes, int n_in,
                              void* d_out, int out_size) {
    const float* diff = (const float*)d_in[0];
    const float* w    = (const float*)d_in[1];
    const int*   ep   = (const int*)d_in[2];
    float*       out  = (float*)d_out;

    k_main<<<B * BPB, 256>>>((const float4*)diff, (const float4*)w, (float4*)out);
    k_select<<<B, STH>>>(diff, out, ep);
}

// round 15
// speedup vs baseline: 1.4853x; 1.0063x over previous
#include <cuda_runtime.h>
#include <cstdint>
#include <cstddef>

// out[b] = weight[b] + top1000_scatter_mask(|difference[b]|), B=64, N=1M/batch.
// R15 = R14 + (a) PDL: k_select launches programmatically and runs its
// preamble during k_main's drain; (b) candidates packed as uint2 (one 64-bit
// memory op per candidate on both sides).

namespace {

constexpr int B      = 64;
constexpr int NPB    = 1 << 20;
constexpr int TOPN   = 1000;
constexpr unsigned CUT = 0x404CCCCDu; // float bits of 3.2f (rank-1000 ~3.29 sigma)
constexpr int BPB    = 1024;
constexpr int DCAP   = 16384;         // dense candidate capacity (mean ~1374)
constexpr int CACHE  = 4096;          // smem candidate cache (mean 1374, +70 sigma)
constexpr int NBIN   = 1024;          // smem hist bins: (key - CUT) >> 14, clamped
constexpr int BCAP   = 512;           // boundary-bin capacity (mean ~13)
constexpr int MAXTIES = 256;
constexpr int STH    = 1024;

__device__ uint2    g_cand[B][DCAP];  // .x = key, .y = idx
__device__ unsigned g_dcnt[B * 32];   // 128B-padded; reset by k_select each replay

__device__ __forceinline__ unsigned keybin(unsigned key) {
    unsigned d = key - CUT;           // key >= CUT on candidate path
    unsigned bi = d >> 14;
    return bi < (unsigned)NBIN ? bi : (unsigned)(NBIN - 1);
}

// Fire-and-forget +1.0 (REDG): no load-modify-store round trip.
__device__ __forceinline__ void scatter1(float* p) {
    atomicAdd(p, 1.0f);               // result unused -> RED.E.ADD.F32
}

// Streaming pass: out = weight; gather |diff| >= 3.2 into dense per-batch arrays.
__global__ void __launch_bounds__(256) k_main(const float4* __restrict__ diff,
                                              const float4* __restrict__ w,
                                              float4* __restrict__ out) {
    __shared__ uint2    s_kv[1024];
    __shared__ unsigned s_n, s_base;
    if (threadIdx.x == 0) s_n = 0u;
    __syncthreads();

    unsigned b    = blockIdx.x & 63u;          // interleaved batch mapping
    unsigned bblk = blockIdx.x >> 6;
    unsigned t    = (b << 18) + bblk * 256u + threadIdx.x;
    float4 d = __ldcs(&diff[t]);
    __stcs(&out[t], __ldcs(&w[t]));

    unsigned e0 = (bblk * 256u + threadIdx.x) << 2;

    unsigned keys[4] = {__float_as_uint(d.x) & 0x7FFFFFFFu,
                        __float_as_uint(d.y) & 0x7FFFFFFFu,
                        __float_as_uint(d.z) & 0x7FFFFFFFu,
                        __float_as_uint(d.w) & 0x7FFFFFFFu};
#pragma unroll
    for (int j = 0; j < 4; ++j) {
        if (keys[j] >= CUT) {                 // ~0.137% of elements
            unsigned p = atomicAdd(&s_n, 1u);
            s_kv[p] = make_uint2(keys[j], e0 + j);
        }
    }
    __syncthreads();

    unsigned n = s_n;
    if (n) {
        if (threadIdx.x == 0)
            s_base = atomicAdd(&g_dcnt[b * 32], n);
        __syncthreads();
        unsigned base = s_base;
        for (unsigned i = threadIdx.x; i < n; i += 256u) {
            unsigned slot = base + i;
            if (slot < (unsigned)DCAP) g_cand[b][slot] = s_kv[i];
        }
    }

    // PDL: allow the dependent k_select grid to begin launching.
    cudaTriggerProgrammaticLaunchCompletion();
}

// Per-batch selection, fully self-contained in SMEM. One block per batch.
__global__ void __launch_bounds__(STH) k_select(const float* __restrict__ diff,
                                                float* __restrict__ out,
                                                const int* __restrict__ ep) {
    __shared__ uint2    s_kv[CACHE];
    __shared__ unsigned hist[NBIN];
    __shared__ unsigned s_wsum[32], s_wsuf[32];
    __shared__ unsigned s_bkey[BCAP];
    __shared__ unsigned s_bidx[BCAP];
    __shared__ unsigned s_bn, s_p0, s_rem;
    __shared__ unsigned s_prefix, s_rem2, s_tcnt;
    __shared__ unsigned s_tidx[MAXTIES];

    int b = blockIdx.x;
    unsigned tid  = threadIdx.x;
    unsigned lane = tid & 31u;
    unsigned wid  = tid >> 5;

    // ---- Preamble (independent of k_main's writes): overlaps its drain ----
    int epoch = ep[0];                         // input buffer, never written
    bool hot = (epoch > 1000) && (epoch < 18000) && (epoch % 200 == 0);
    hist[tid] = 0u;
    if (tid == 0) s_bn = 0u;

    // ---- Wait for k_main's results to be visible ----
    cudaGridDependencySynchronize();

    unsigned raw = g_dcnt[b * 32];
    bool fast = (raw >= (unsigned)TOPN) && (raw <= (unsigned)DCAP);
    bool sfit = fast && (raw <= (unsigned)CACHE);
    size_t gbase = (size_t)b * (size_t)NPB;
    unsigned dom = fast ? raw : (unsigned)NPB;

    bool done = !hot;

    if (hot && fast) {
        // ---- Pass A: load candidates once (uint2), stash, build smem hist ----
        __syncthreads();                       // hist zero visible to all
        for (unsigned i = tid; i < dom; i += STH) {
            uint2 kv = g_cand[b][i];
            if (sfit) s_kv[i] = kv;
            atomicAdd(&hist[keybin(kv.x)], 1u);   // ~370 live bins: no hot spot
        }
        __syncthreads();

        // ---- Suffix scan over 1024 bins: exactly 1 bin per thread ----
        unsigned P = hist[tid];
        unsigned s = P;
#pragma unroll
        for (unsigned off = 1; off < 32; off <<= 1) {
            unsigned v = __shfl_down_sync(0xFFFFFFFFu, s, off);
            if (lane + off < 32u) s += v;
        }
        if (lane == 0) s_wsum[wid] = s;          // whole-warp sum
        __syncthreads();
        if (wid == 0) {
            unsigned tsum = s_wsum[lane];
            unsigned ss = tsum;
#pragma unroll
            for (unsigned off = 1; off < 32; off <<= 1) {
                unsigned v = __shfl_down_sync(0xFFFFFFFFu, ss, off);
                if (lane + off < 32u) ss += v;
            }
            s_wsuf[lane] = ss - tsum;            // warps strictly after
        }
        __syncthreads();
        unsigned above = (s + s_wsuf[wid]) - P;  // keys in bins strictly above tid
        if (above < (unsigned)TOPN && above + P >= (unsigned)TOPN) {
            s_p0 = tid; s_rem = (unsigned)TOPN - above;
        }
        __syncthreads();

        unsigned p0  = s_p0;
        unsigned rem = s_rem;
        unsigned m   = hist[p0];

        if (m <= (unsigned)BCAP) {
            // ---- Pass B (smem): REDG-scatter winners, collect boundary bin ----
            for (unsigned i = tid; i < dom; i += STH) {
                uint2 kv = sfit ? s_kv[i] : g_cand[b][i];
                unsigned bi = keybin(kv.x);
                if (bi > p0) {
                    scatter1(&out[gbase + kv.y]);
                } else if (bi == p0) {
                    unsigned p = atomicAdd(&s_bn, 1u);
                    s_bkey[p] = kv.x;                    // p < m <= BCAP
                    s_bidx[p] = kv.y;
                }
            }
            __syncthreads();
            // ---- Exact boundary ranking (key desc, idx asc) ----
            for (unsigned u = tid; u < m; u += STH) {
                unsigned mk = s_bkey[u], mi = s_bidx[u];
                unsigned rank = 0u;
                for (unsigned j = 0; j < m; ++j) {
                    unsigned kj = s_bkey[j];
                    rank += (kj > mk || (kj == mk && s_bidx[j] < mi)) ? 1u : 0u;
                }
                if (rank < rem) scatter1(&out[gbase + mi]);
            }
            done = true;
        }
        __syncthreads();
    }

    if (!done) {
        // ==== Fallback: exact 4-round radix select over full batch ====
        if (tid == 0) { s_prefix = 0u; s_rem2 = (unsigned)TOPN; s_tcnt = 0u; }
        __syncthreads();

        auto getkey = [&](unsigned i) -> unsigned {
            if (fast) return g_cand[b][i].x;
            return __float_as_uint(diff[gbase + i]) & 0x7FFFFFFFu;
        };
        auto getidx = [&](unsigned i) -> unsigned {
            if (fast) return g_cand[b][i].y;
            return i;
        };

        const int      SH[4] = {23, 15, 7, 0};
        const unsigned BM[4] = {255u, 255u, 255u, 127u};
#pragma unroll 1
        for (int r = 0; r < 4; ++r) {
            if (tid < 256u) hist[tid] = 0u;
            __syncthreads();
            int      sh     = SH[r];
            int      hish   = sh + (r == 3 ? 7 : 8);
            unsigned prefix = s_prefix;
            for (unsigned i = tid; i < dom; i += STH) {
                unsigned key = getkey(i);
                if (((key ^ prefix) >> hish) == 0u)
                    atomicAdd(&hist[(key >> sh) & BM[r]], 1u);
            }
            __syncthreads();
            if (tid == 0) {
                unsigned need = s_rem2, acc = 0u;
                int bin = (int)BM[r];
                for (; bin > 0; --bin) {
                    unsigned c = hist[bin];
                    if (acc + c >= need) break;
                    acc += c;
                }
                s_rem2   = need - acc;
                s_prefix = prefix | ((unsigned)bin << sh);
            }
            __syncthreads();
        }

        unsigned thr = s_prefix;
        unsigned req = s_rem2;

        for (unsigned i = tid; i < dom; i += STH) {
            unsigned key = getkey(i);
            if (key > thr) {
                scatter1(&out[gbase + getidx(i)]);
            } else if (key == thr) {
                unsigned p = atomicAdd(&s_tcnt, 1u);
                if (p < (unsigned)MAXTIES) s_tidx[p] = getidx(i);
            }
        }
        __syncthreads();

        unsigned tc = s_tcnt;
        if (tc <= (unsigned)MAXTIES) {
            for (unsigned u = tid; u < tc; u += STH) {
                unsigned my = s_tidx[u], rank = 0u;
                for (unsigned j = 0; j < tc; ++j) rank += (s_tidx[j] < my) ? 1u : 0u;
                if (rank < req) scatter1(&out[gbase + my]);
            }
        } else {
            for (unsigned i = tid; i < dom; i += STH) {
                unsigned key = getkey(i);
                if (key != thr) continue;
                unsigned idx = getidx(i), rank = 0u;
                for (unsigned j = 0; j < dom; ++j) {
                    if (getkey(j) == thr && getidx(j) < idx) ++rank;
                }
                if (rank < req) scatter1(&out[gbase + idx]);
            }
        }
        __syncthreads();
    }

    if (tid == 0) g_dcnt[b * 32] = 0u;   // reset for next graph replay
}

} // namespace

extern "C" void kernel_launch(void* const* d_in, const int* in_sizes, int n_in,
                              void* d_out, int out_size) {
    const float* diff = (const float*)d_in[0];
    const float* w    = (const float*)d_in[1];
    const int*   ep   = (const int*)d_in[2];
    float*       out  = (float*)d_out;

    k_main<<<B * BPB, 256>>>((const float4*)diff, (const float4*)w, (float4*)out);

    // k_select with programmatic dependent launch (overlaps k_main's drain).
    cudaLaunchConfig_t cfg = {};
    cfg.gridDim  = dim3(B);
    cfg.blockDim = dim3(STH);
    cfg.stream   = 0;                   // same (legacy default) stream as k_main
    cudaLaunchAttribute attr[1];
    attr[0].id = cudaLaunchAttributeProgrammaticStreamSerialization;
    attr[0].val.programmaticStreamSerializationAllowed = 1;
    cfg.attrs    = attr;
    cfg.numAttrs = 1;
    cudaLaunchKernelEx(&cfg, k_select, diff, out, ep);
}

// round 16
// speedup vs baseline: 1.5739x; 1.0597x over previous
#include <cuda_runtime.h>
#include <cstdint>
#include <cstddef>

// out[b] = weight[b] + top1000_scatter_mask(|difference[b]|), B=64, N=1M/batch.
// R16 = R15 + k_main MLP boost: 2 float4 per thread, all 4 independent
// LDG.128 front-batched before any dependent work (MLP_p1 2 -> 4).

namespace {

constexpr int B      = 64;
constexpr int NPB    = 1 << 20;
constexpr int TOPN   = 1000;
constexpr unsigned CUT = 0x404CCCCDu; // float bits of 3.2f (rank-1000 ~3.29 sigma)
constexpr int BPB    = 512;           // blocks per batch (2048 elems per block)
constexpr int DCAP   = 16384;         // dense candidate capacity (mean ~1374)
constexpr int CACHE  = 4096;          // smem candidate cache (mean 1374, +70 sigma)
constexpr int NBIN   = 1024;          // smem hist bins: (key - CUT) >> 14, clamped
constexpr int BCAP   = 512;           // boundary-bin capacity (mean ~13)
constexpr int MAXTIES = 256;
constexpr int STH    = 1024;

__device__ uint2    g_cand[B][DCAP];  // .x = key, .y = idx
__device__ unsigned g_dcnt[B * 32];   // 128B-padded; reset by k_select each replay

__device__ __forceinline__ unsigned keybin(unsigned key) {
    unsigned d = key - CUT;           // key >= CUT on candidate path
    unsigned bi = d >> 14;
    return bi < (unsigned)NBIN ? bi : (unsigned)(NBIN - 1);
}

__device__ __forceinline__ void scatter1(float* p) {
    atomicAdd(p, 1.0f);               // result unused -> RED.E.ADD.F32 (REDG)
}

// Streaming pass: out = weight; gather |diff| >= 3.2 into dense per-batch arrays.
// 2 float4 per thread; 4 independent loads issued before any dependent work.
__global__ void __launch_bounds__(256) k_main(const float4* __restrict__ diff,
                                              const float4* __restrict__ w,
                                              float4* __restrict__ out) {
    __shared__ uint2    s_kv[2048];            // worst case: every element selected
    __shared__ unsigned s_n, s_base;
    unsigned tid = threadIdx.x;
    if (tid == 0) s_n = 0u;
    __syncthreads();

    unsigned b    = blockIdx.x & 63u;          // interleaved batch mapping
    unsigned bblk = blockIdx.x >> 6;           // 0..511
    unsigned base = (b << 18) + bblk * 512u;   // float4 index of block start
    unsigned t0 = base + tid;
    unsigned t1 = base + 256u + tid;

    // Front-batched independent loads (MLP_p1 = 4)
    float4 d0 = __ldcs(&diff[t0]);
    float4 d1 = __ldcs(&diff[t1]);
    float4 w0 = __ldcs(&w[t0]);
    float4 w1 = __ldcs(&w[t1]);
    __stcs(&out[t0], w0);
    __stcs(&out[t1], w1);

    unsigned e0 = (bblk * 512u + tid) << 2;            // element idx of d0.x
    unsigned e1 = (bblk * 512u + 256u + tid) << 2;     // element idx of d1.x

    unsigned k0[4] = {__float_as_uint(d0.x) & 0x7FFFFFFFu,
                      __float_as_uint(d0.y) & 0x7FFFFFFFu,
                      __float_as_uint(d0.z) & 0x7FFFFFFFu,
                      __float_as_uint(d0.w) & 0x7FFFFFFFu};
    unsigned k1[4] = {__float_as_uint(d1.x) & 0x7FFFFFFFu,
                      __float_as_uint(d1.y) & 0x7FFFFFFFu,
                      __float_as_uint(d1.z) & 0x7FFFFFFFu,
                      __float_as_uint(d1.w) & 0x7FFFFFFFu};
#pragma unroll
    for (int j = 0; j < 4; ++j) {
        if (k0[j] >= CUT) {                    // ~0.137% of elements
            unsigned p = atomicAdd(&s_n, 1u);
            s_kv[p] = make_uint2(k0[j], e0 + j);
        }
    }
#pragma unroll
    for (int j = 0; j < 4; ++j) {
        if (k1[j] >= CUT) {
            unsigned p = atomicAdd(&s_n, 1u);
            s_kv[p] = make_uint2(k1[j], e1 + j);
        }
    }
    __syncthreads();

    unsigned n = s_n;
    if (n) {
        if (tid == 0)
            s_base = atomicAdd(&g_dcnt[b * 32], n);
        __syncthreads();
        unsigned bs = s_base;
        for (unsigned i = tid; i < n; i += 256u) {
            unsigned slot = bs + i;
            if (slot < (unsigned)DCAP) g_cand[b][slot] = s_kv[i];
        }
    }

    // PDL: allow the dependent k_select grid to begin launching.
    cudaTriggerProgrammaticLaunchCompletion();
}

// Per-batch selection, fully self-contained in SMEM. One block per batch.
__global__ void __launch_bounds__(STH) k_select(const float* __restrict__ diff,
                                                float* __restrict__ out,
                                                const int* __restrict__ ep) {
    __shared__ uint2    s_kv[CACHE];
    __shared__ unsigned hist[NBIN];
    __shared__ unsigned s_wsum[32], s_wsuf[32];
    __shared__ unsigned s_bkey[BCAP];
    __shared__ unsigned s_bidx[BCAP];
    __shared__ unsigned s_bn, s_p0, s_rem;
    __shared__ unsigned s_prefix, s_rem2, s_tcnt;
    __shared__ unsigned s_tidx[MAXTIES];

    int b = blockIdx.x;
    unsigned tid  = threadIdx.x;
    unsigned lane = tid & 31u;
    unsigned wid  = tid >> 5;

    // ---- Preamble (independent of k_main's writes): overlaps its drain ----
    int epoch = ep[0];
    bool hot = (epoch > 1000) && (epoch < 18000) && (epoch % 200 == 0);
    hist[tid] = 0u;
    if (tid == 0) s_bn = 0u;

    cudaGridDependencySynchronize();

    unsigned raw = g_dcnt[b * 32];
    bool fast = (raw >= (unsigned)TOPN) && (raw <= (unsigned)DCAP);
    bool sfit = fast && (raw <= (unsigned)CACHE);
    size_t gbase = (size_t)b * (size_t)NPB;
    unsigned dom = fast ? raw : (unsigned)NPB;

    bool done = !hot;

    if (hot && fast) {
        // ---- Pass A: load candidates once (uint2), stash, build smem hist ----
        __syncthreads();
        for (unsigned i = tid; i < dom; i += STH) {
            uint2 kv = g_cand[b][i];
            if (sfit) s_kv[i] = kv;
            atomicAdd(&hist[keybin(kv.x)], 1u);   // ~370 live bins: no hot spot
        }
        __syncthreads();

        // ---- Suffix scan over 1024 bins: exactly 1 bin per thread ----
        unsigned P = hist[tid];
        unsigned s = P;
#pragma unroll
        for (unsigned off = 1; off < 32; off <<= 1) {
            unsigned v = __shfl_down_sync(0xFFFFFFFFu, s, off);
            if (lane + off < 32u) s += v;
        }
        if (lane == 0) s_wsum[wid] = s;
        __syncthreads();
        if (wid == 0) {
            unsigned tsum = s_wsum[lane];
            unsigned ss = tsum;
#pragma unroll
            for (unsigned off = 1; off < 32; off <<= 1) {
                unsigned v = __shfl_down_sync(0xFFFFFFFFu, ss, off);
                if (lane + off < 32u) ss += v;
            }
            s_wsuf[lane] = ss - tsum;
        }
        __syncthreads();
        unsigned above = (s + s_wsuf[wid]) - P;
        if (above < (unsigned)TOPN && above + P >= (unsigned)TOPN) {
            s_p0 = tid; s_rem = (unsigned)TOPN - above;
        }
        __syncthreads();

        unsigned p0  = s_p0;
        unsigned rem = s_rem;
        unsigned m   = hist[p0];

        if (m <= (unsigned)BCAP) {
            // ---- Pass B (smem): REDG-scatter winners, collect boundary bin ----
            for (unsigned i = tid; i < dom; i += STH) {
                uint2 kv = sfit ? s_kv[i] : g_cand[b][i];
                unsigned bi = keybin(kv.x);
                if (bi > p0) {
                    scatter1(&out[gbase + kv.y]);
                } else if (bi == p0) {
                    unsigned p = atomicAdd(&s_bn, 1u);
                    s_bkey[p] = kv.x;                    // p < m <= BCAP
                    s_bidx[p] = kv.y;
                }
            }
            __syncthreads();
            // ---- Exact boundary ranking (key desc, idx asc) ----
            for (unsigned u = tid; u < m; u += STH) {
                unsigned mk = s_bkey[u], mi = s_bidx[u];
                unsigned rank = 0u;
                for (unsigned j = 0; j < m; ++j) {
                    unsigned kj = s_bkey[j];
                    rank += (kj > mk || (kj == mk && s_bidx[j] < mi)) ? 1u : 0u;
                }
                if (rank < rem) scatter1(&out[gbase + mi]);
            }
            done = true;
        }
        __syncthreads();
    }

    if (!done) {
        // ==== Fallback: exact 4-round radix select over full batch ====
        if (tid == 0) { s_prefix = 0u; s_rem2 = (unsigned)TOPN; s_tcnt = 0u; }
        __syncthreads();

        auto getkey = [&](unsigned i) -> unsigned {
            if (fast) return g_cand[b][i].x;
            return __float_as_uint(diff[gbase + i]) & 0x7FFFFFFFu;
        };
        auto getidx = [&](unsigned i) -> unsigned {
            if (fast) return g_cand[b][i].y;
            return i;
        };

        const int      SH[4] = {23, 15, 7, 0};
        const unsigned BM[4] = {255u, 255u, 255u, 127u};
#pragma unroll 1
        for (int r = 0; r < 4; ++r) {
            if (tid < 256u) hist[tid] = 0u;
            __syncthreads();
            int      sh     = SH[r];
            int      hish   = sh + (r == 3 ? 7 : 8);
            unsigned prefix = s_prefix;
            for (unsigned i = tid; i < dom; i += STH) {
                unsigned key = getkey(i);
                if (((key ^ prefix) >> hish) == 0u)
                    atomicAdd(&hist[(key >> sh) & BM[r]], 1u);
            }
            __syncthreads();
            if (tid == 0) {
                unsigned need = s_rem2, acc = 0u;
                int bin = (int)BM[r];
                for (; bin > 0; --bin) {
                    unsigned c = hist[bin];
                    if (acc + c >= need) break;
                    acc += c;
                }
                s_rem2   = need - acc;
                s_prefix = prefix | ((unsigned)bin << sh);
            }
            __syncthreads();
        }

        unsigned thr = s_prefix;
        unsigned req = s_rem2;

        for (unsigned i = tid; i < dom; i += STH) {
            unsigned key = getkey(i);
            if (key > thr) {
                scatter1(&out[gbase + getidx(i)]);
            } else if (key == thr) {
                unsigned p = atomicAdd(&s_tcnt, 1u);
                if (p < (unsigned)MAXTIES) s_tidx[p] = getidx(i);
            }
        }
        __syncthreads();

        unsigned tc = s_tcnt;
        if (tc <= (unsigned)MAXTIES) {
            for (unsigned u = tid; u < tc; u += STH) {
                unsigned my = s_tidx[u], rank = 0u;
                for (unsigned j = 0; j < tc; ++j) rank += (s_tidx[j] < my) ? 1u : 0u;
                if (rank < req) scatter1(&out[gbase + my]);
            }
        } else {
            for (unsigned i = tid; i < dom; i += STH) {
                unsigned key = getkey(i);
                if (key != thr) continue;
                unsigned idx = getidx(i), rank = 0u;
                for (unsigned j = 0; j < dom; ++j) {
                    if (getkey(j) == thr && getidx(j) < idx) ++rank;
                }
                if (rank < req) scatter1(&out[gbase + idx]);
            }
        }
        __syncthreads();
    }

    if (tid == 0) g_dcnt[b * 32] = 0u;   // reset for next graph replay
}

} // namespace

extern "C" void kernel_launch(void* const* d_in, const int* in_sizes, int n_in,
                              void* d_out, int out_size) {
    const float* diff = (const float*)d_in[0];
    const float* w    = (const float*)d_in[1];
    const int*   ep   = (const int*)d_in[2];
    float*       out  = (float*)d_out;

    k_main<<<B * BPB, 256>>>((const float4*)diff, (const float4*)w, (float4*)out);

    // k_select with programmatic dependent launch (overlaps k_main's drain).
    cudaLaunchConfig_t cfg = {};
    cfg.gridDim  = dim3(B);
    cfg.blockDim = dim3(STH);
    cfg.stream   = 0;
    cudaLaunchAttribute attr[1];
    attr[0].id = cudaLaunchAttributeProgrammaticStreamSerialization;
    attr[0].val.programmaticStreamSerializationAllowed = 1;
    cfg.attrs    = attr;
    cfg.numAttrs = 1;
    cudaLaunchKernelEx(&cfg, k_select, diff, out, ep);
}